// round 15
// baseline (speedup 1.0000x reference)
#include <cuda_runtime.h>
#include <cuda_bf16.h>
#include <cstdint>
#include <math.h>

#define EPSV 1e-5f
#define BATCH 4096
#define HDIM 4096
#define DIN 1024
#define NOUT 2000
#define NOUT_PAD 2048

// ---------------- scratch (device globals: allocation-free, <=134MB total) ----------------
__device__ __align__(16) __nv_bfloat16 g_A[BATCH * HDIM];   // quantized activations (int-valued bf16)
__device__ __align__(16) __nv_bfloat16 g_W[HDIM * HDIM];    // ternary weights (bf16), reused per layer
__device__ float  g_C[BATCH * HDIM];                        // raw GEMM output (integer-valued fp32)
__device__ float  g_rs[BATCH];                              // per-row activation dequant (1/scale)
__device__ float  g_wpart[4][1024];                         // per-block partial |W| sums
__device__ double g_wsum[4];                                // total |W| sums (published by tern block 0)

// ================= helpers =================
__device__ __forceinline__ uint32_t smem_u32(const void* p) {
    uint32_t a;
    asm("{ .reg .u64 t; cvta.to.shared.u64 t, %1; cvt.u32.u64 %0, t; }" : "=r"(a) : "l"(p));
    return a;
}
__device__ __forceinline__ void cp16(uint32_t dst, const void* src) {
    asm volatile("cp.async.cg.shared.global [%0], [%1], 16;\n" :: "r"(dst), "l"(src));
}
#define CP_COMMIT() asm volatile("cp.async.commit_group;\n" ::: "memory")
#define CP_WAIT1()  asm volatile("cp.async.wait_group 1;\n" ::: "memory")

__device__ __forceinline__ void ldsm_x4(uint32_t& r0, uint32_t& r1, uint32_t& r2, uint32_t& r3,
                                        uint32_t addr) {
    asm volatile("ldmatrix.sync.aligned.m8n8.x4.shared.b16 {%0,%1,%2,%3}, [%4];"
                 : "=r"(r0), "=r"(r1), "=r"(r2), "=r"(r3) : "r"(addr));
}

// ---------------- reductions ----------------
__device__ __forceinline__ float blockReduceSum(float val) {
    __shared__ float sm[32];
    int lane = threadIdx.x & 31, wid = threadIdx.x >> 5;
#pragma unroll
    for (int o = 16; o; o >>= 1) val += __shfl_xor_sync(0xffffffffu, val, o);
    if (lane == 0) sm[wid] = val;
    __syncthreads();
    if (wid == 0) {
        val = (lane < (blockDim.x >> 5)) ? sm[lane] : 0.f;
#pragma unroll
        for (int o = 16; o; o >>= 1) val += __shfl_xor_sync(0xffffffffu, val, o);
        if (lane == 0) sm[0] = val;
    }
    __syncthreads();
    float r = sm[0];
    __syncthreads();
    return r;
}

__device__ __forceinline__ float blockReduceMax(float val) {
    __shared__ float sm[32];
    int lane = threadIdx.x & 31, wid = threadIdx.x >> 5;
#pragma unroll
    for (int o = 16; o; o >>= 1) val = fmaxf(val, __shfl_xor_sync(0xffffffffu, val, o));
    if (lane == 0) sm[wid] = val;
    __syncthreads();
    if (wid == 0) {
        val = (lane < (blockDim.x >> 5)) ? sm[lane] : 0.f;
#pragma unroll
        for (int o = 16; o; o >>= 1) val = fmaxf(val, __shfl_xor_sync(0xffffffffu, val, o));
        if (lane == 0) sm[0] = val;
    }
    __syncthreads();
    float r = sm[0];
    __syncthreads();
    return r;
}

// ---------------- weight abs-mean pass 1 (fp32, deterministic, MLP-4) ----------------
__global__ void wsum_kernel(const float* __restrict__ W, int n, int idx) {
    const float4* W4 = (const float4*)W;
    const int n4 = n >> 2;
    const int str = gridDim.x * blockDim.x;
    float s = 0.0f;
    int i = blockIdx.x * blockDim.x + threadIdx.x;
    for (; i + 3 * str < n4; i += 4 * str) {
        float4 a = W4[i];
        float4 b = W4[i + str];
        float4 c = W4[i + 2 * str];
        float4 d = W4[i + 3 * str];
        s += fabsf(a.x) + fabsf(a.y) + fabsf(a.z) + fabsf(a.w);
        s += fabsf(b.x) + fabsf(b.y) + fabsf(b.z) + fabsf(b.w);
        s += fabsf(c.x) + fabsf(c.y) + fabsf(c.z) + fabsf(c.w);
        s += fabsf(d.x) + fabsf(d.y) + fabsf(d.z) + fabsf(d.w);
    }
    for (; i < n4; i += str) {
        float4 a = W4[i];
        s += fabsf(a.x) + fabsf(a.y) + fabsf(a.z) + fabsf(a.w);
    }
    __shared__ float sm[256];
    sm[threadIdx.x] = s;
    __syncthreads();
    for (int o = 128; o; o >>= 1) {
        if (threadIdx.x < o) sm[threadIdx.x] += sm[threadIdx.x + o];
        __syncthreads();
    }
    if (threadIdx.x == 0) g_wpart[idx][blockIdx.x] = sm[0];
}

// ---------------- ternarize (computes mean in-block from partials; no wreduce kernel) ----------------
__global__ void tern_kernel(const float* __restrict__ W, int rows, int cols,
                            int rows_pad, int idx, double count) {
    // replicate wreduce_one's exact fp64 summation order for bitwise-identical mean
    __shared__ double smd[256];
    {
        double s = 0.0;
        for (int i = threadIdx.x; i < 1024; i += 256) s += (double)g_wpart[idx][i];
        smd[threadIdx.x] = s;
        __syncthreads();
        for (int o = 128; o; o >>= 1) {
            if (threadIdx.x < o) smd[threadIdx.x] += smd[threadIdx.x + o];
            __syncthreads();
        }
    }
    double wsum = smd[0];
    if (blockIdx.x == 0 && threadIdx.x == 0) g_wsum[idx] = wsum;  // publish for LN/epilogue

    float mean = (float)(wsum / count);
    float scale = 1.0f / fmaxf(mean, EPSV);
    int n16 = (rows_pad * cols) >> 4;   // cols % 16 == 0, chunks never straddle rows
    int str = gridDim.x * blockDim.x;
    for (int i16 = blockIdx.x * blockDim.x + threadIdx.x; i16 < n16; i16 += str) {
        int r = (i16 << 4) / cols;
        __nv_bfloat16 o[16];
        if (r < rows) {
            const float4* p = (const float4*)(W + ((size_t)i16 << 4));
            float4 a = p[0], b = p[1], c = p[2], d = p[3];
            float v[16] = {a.x, a.y, a.z, a.w, b.x, b.y, b.z, b.w,
                           c.x, c.y, c.z, c.w, d.x, d.y, d.z, d.w};
#pragma unroll
            for (int k = 0; k < 16; k++) {
                float t = rintf(v[k] * scale);
                o[k] = __float2bfloat16(fminf(fmaxf(t, -1.0f), 1.0f));
            }
        } else {
#pragma unroll
            for (int k = 0; k < 16; k++) o[k] = __float2bfloat16(0.0f);
        }
        *(uint4*)(g_W + ((size_t)i16 << 4)) = *(const uint4*)o;
        *(uint4*)(g_W + ((size_t)i16 << 4) + 8) = *(const uint4*)(o + 8);
    }
}

// ---------------- quantize input x (float4 path) ----------------
__global__ void actquant_x(const float* __restrict__ x) {
    int row = blockIdx.x;
    const float4* xr4 = (const float4*)(x + (size_t)row * DIN);
    float4 t = xr4[threadIdx.x];   // 256 threads x 4 = 1024
    float m = fmaxf(fmaxf(fabsf(t.x), fabsf(t.y)), fmaxf(fabsf(t.z), fabsf(t.w)));
    m = blockReduceMax(m);
    float scale = 127.0f / fmaxf(m, EPSV);
    float v[4] = {t.x, t.y, t.z, t.w};
    __nv_bfloat16 o[4];
#pragma unroll
    for (int k = 0; k < 4; k++) {
        float q = rintf(v[k] * scale);
        q = fminf(fmaxf(q, -128.0f), 127.0f);
        o[k] = __float2bfloat16(q);
    }
    *(uint2*)(g_A + (size_t)row * DIN + threadIdx.x * 4) = *(const uint2*)o;
    if (threadIdx.x == 0) g_rs[row] = 1.0f / scale;
}

// ================ bf16 HMMA GEMM: C[M,N] = g_A[M,K] @ g_W[N,K]^T ================
// 128x128 CTA tile, 8 warps (2x4), warp tile 64x32, K chunk 64,
// 3-stage cp.async ring with ONE barrier per chunk, ldmatrix fragment loads.
// If outp != nullptr (layer 3): fused sigmoid epilogue writes final outputs.
#define SROWE 72
#define STAGE_B (128 * SROWE * 2)          // 18432
#define GEMM_SMEM (6 * STAGE_B)            // 110592

__global__ __launch_bounds__(256, 2) void gemm_bf16(int K, int ldc,
                                                    float* __restrict__ outp, double count) {
    extern __shared__ __align__(16) char smem[];
    const uint32_t sbase = smem_u32(smem);
    const int tid = threadIdx.x;
    const int lane = tid & 31;
    const int wid = tid >> 5;
    const int wm = (wid >> 2) * 64;   // warp M offset (0/64)
    const int wn = (wid & 3) * 32;    // warp N offset (0..96)
    const int bm = blockIdx.y * 128;
    const int bn = blockIdx.x * 128;
    const int NC = K >> 6;            // 64-wide K chunks

    const __nv_bfloat16* Ag = g_A + (size_t)bm * K;
    const __nv_bfloat16* Bg = g_W + (size_t)bn * K;

    const int lrow = tid >> 1;            // 0..127 row
    const int lj = (tid & 1) * 4;         // 16B chunks {0..3} or {4..7}

    auto load_chunk = [&](int c, int buf) {
        int k0 = c << 6;
        uint32_t da = sbase + buf * 2 * STAGE_B;
        uint32_t db = da + STAGE_B;
        const __nv_bfloat16* arow = Ag + (size_t)lrow * K + k0;
        const __nv_bfloat16* brow = Bg + (size_t)lrow * K + k0;
        uint32_t off = lrow * (SROWE * 2) + lj * 16;
#pragma unroll
        for (int j = 0; j < 4; j++) {
            cp16(da + off + j * 16, arow + (lj + j) * 8);
            cp16(db + off + j * 16, brow + (lj + j) * 8);
        }
    };

    float acc[4][4][4];
#pragma unroll
    for (int i = 0; i < 4; i++)
#pragma unroll
        for (int j = 0; j < 4; j++)
#pragma unroll
            for (int k = 0; k < 4; k++) acc[i][j][k] = 0.0f;

    // prologue: chunks 0 and 1 in flight
    load_chunk(0, 0);
    CP_COMMIT();
    if (NC > 1) load_chunk(1, 1);
    CP_COMMIT();

    // ldmatrix lane addressing
    const int a_row_off = (lane & 7) + ((lane >> 3) & 1) * 8;
    const int a_col_off = (lane >> 4) * 8;
    const int b_row_off = (lane & 7) + ((lane >> 4) & 1) * 8;
    const int b_col_off = ((lane >> 3) & 1) * 8;

    int buf = 0;          // = c % 3
    int buf2 = 2;         // = (c+2) % 3
    for (int c = 0; c < NC; c++) {
        CP_WAIT1();       // chunk c resident (<=1 newer group outstanding)
        __syncthreads();  // prior reads of buf2 done across CTA

        if (c + 2 < NC) load_chunk(c + 2, buf2);
        CP_COMMIT();      // keep group count in lockstep

        uint32_t Abase = sbase + buf * 2 * STAGE_B;
        uint32_t Bbase = Abase + STAGE_B;

#pragma unroll
        for (int kk = 0; kk < 64; kk += 16) {
            uint32_t af[4][4];
#pragma unroll
            for (int mi = 0; mi < 4; mi++) {
                uint32_t addr = Abase + (uint32_t)((wm + mi * 16 + a_row_off) * (SROWE * 2)
                                                   + (kk + a_col_off) * 2);
                ldsm_x4(af[mi][0], af[mi][1], af[mi][2], af[mi][3], addr);
            }
            uint32_t bfr[4][2];
#pragma unroll
            for (int nip = 0; nip < 2; nip++) {
                uint32_t addr = Bbase + (uint32_t)((wn + nip * 16 + b_row_off) * (SROWE * 2)
                                                   + (kk + b_col_off) * 2);
                ldsm_x4(bfr[nip * 2][0], bfr[nip * 2][1],
                        bfr[nip * 2 + 1][0], bfr[nip * 2 + 1][1], addr);
            }
#pragma unroll
            for (int mi = 0; mi < 4; mi++)
#pragma unroll
                for (int ni = 0; ni < 4; ni++)
                    asm volatile(
                        "mma.sync.aligned.m16n8k16.row.col.f32.bf16.bf16.f32 "
                        "{%0,%1,%2,%3}, {%4,%5,%6,%7}, {%8,%9}, {%0,%1,%2,%3};\n"
                        : "+f"(acc[mi][ni][0]), "+f"(acc[mi][ni][1]),
                          "+f"(acc[mi][ni][2]), "+f"(acc[mi][ni][3])
                        : "r"(af[mi][0]), "r"(af[mi][1]), "r"(af[mi][2]), "r"(af[mi][3]),
                          "r"(bfr[ni][0]), "r"(bfr[ni][1]));
        }
        buf = (buf == 2) ? 0 : buf + 1;
        buf2 = (buf2 == 2) ? 0 : buf2 + 1;
    }

    if (outp == nullptr) {
#pragma unroll
        for (int mi = 0; mi < 4; mi++) {
#pragma unroll
            for (int ni = 0; ni < 4; ni++) {
                int r = bm + wm + mi * 16 + (lane >> 2);
                int cc = bn + wn + ni * 8 + (lane & 3) * 2;
                *(float2*)&g_C[(size_t)r * ldc + cc] = make_float2(acc[mi][ni][0], acc[mi][ni][1]);
                *(float2*)&g_C[(size_t)(r + 8) * ldc + cc] = make_float2(acc[mi][ni][2], acc[mi][ni][3]);
            }
        }
    } else {
        // fused final epilogue: logits -> sigmoid outputs, skip padded cols
        float wmean = fmaxf((float)(g_wsum[3] / count), EPSV);
#pragma unroll
        for (int mi = 0; mi < 4; mi++) {
            int r0 = bm + wm + mi * 16 + (lane >> 2);
            float f0 = __ldg(&g_rs[r0]) * wmean;
            float f1 = __ldg(&g_rs[r0 + 8]) * wmean;
#pragma unroll
            for (int ni = 0; ni < 4; ni++) {
                int cc = bn + wn + ni * 8 + (lane & 3) * 2;
                if (cc < 2000) {
                    float va0 = acc[mi][ni][0] * f0, va1 = acc[mi][ni][1] * f0;
                    float vb0 = acc[mi][ni][2] * f1, vb1 = acc[mi][ni][3] * f1;
                    size_t base0, base1;
                    float kmul, kadd;
                    if (cc < 1000) {            // mz half
                        base0 = (size_t)r0 * 1000 + cc;
                        base1 = (size_t)(r0 + 8) * 1000 + cc;
                        kmul = 999.0f; kadd = 1.0f;
                    } else {                    // intensity half
                        base0 = (size_t)BATCH * 1000 + (size_t)r0 * 1000 + (cc - 1000);
                        base1 = (size_t)BATCH * 1000 + (size_t)(r0 + 8) * 1000 + (cc - 1000);
                        kmul = 100.0f; kadd = 0.0f;
                    }
                    *(float2*)&outp[base0] = make_float2(
                        kmul / (1.0f + __expf(-va0)) + kadd,
                        kmul / (1.0f + __expf(-va1)) + kadd);
                    *(float2*)&outp[base1] = make_float2(
                        kmul / (1.0f + __expf(-vb0)) + kadd,
                        kmul / (1.0f + __expf(-vb1)) + kadd);
                }
            }
        }
    }
}

// ---------------- fused scale + LayerNorm + SiLU + re-quantize (float4 path) ----------------
__global__ void ln_silu_quant(const float* __restrict__ gamma, const float* __restrict__ beta,
                              int widx, double count) {
    int row = blockIdx.x;
    float wmean = fmaxf((float)(g_wsum[widx] / count), EPSV);
    float f = g_rs[row] * wmean;
    const float4* cr4 = (const float4*)(g_C + (size_t)row * HDIM);
    const float4* g4 = (const float4*)gamma;
    const float4* b4 = (const float4*)beta;

    float v[16];
    float s = 0.0f;
#pragma unroll
    for (int i = 0; i < 4; i++) {
        float4 t = cr4[threadIdx.x + i * 256];
        v[i * 4 + 0] = t.x * f; v[i * 4 + 1] = t.y * f;
        v[i * 4 + 2] = t.z * f; v[i * 4 + 3] = t.w * f;
        s += v[i * 4 + 0] + v[i * 4 + 1] + v[i * 4 + 2] + v[i * 4 + 3];
    }
    s = blockReduceSum(s);
    float mu = s * (1.0f / HDIM);

    float s2 = 0.0f;
#pragma unroll
    for (int i = 0; i < 16; i++) {
        float d = v[i] - mu;
        s2 += d * d;
    }
    s2 = blockReduceSum(s2);
    float inv_std = rsqrtf(s2 * (1.0f / HDIM) + EPSV);

    float y[16];
    float mx = 0.0f;
#pragma unroll
    for (int i = 0; i < 4; i++) {
        float4 gg = g4[threadIdx.x + i * 256];
        float4 bb = b4[threadIdx.x + i * 256];
        float gv[4] = {gg.x, gg.y, gg.z, gg.w};
        float bv[4] = {bb.x, bb.y, bb.z, bb.w};
#pragma unroll
        for (int k = 0; k < 4; k++) {
            float t = (v[i * 4 + k] - mu) * inv_std * gv[k] + bv[k];
            t = t / (1.0f + __expf(-t));  // silu
            y[i * 4 + k] = t;
            mx = fmaxf(mx, fabsf(t));
        }
    }
    mx = blockReduceMax(mx);
    float scale = 127.0f / fmaxf(mx, EPSV);
#pragma unroll
    for (int i = 0; i < 4; i++) {
        __nv_bfloat16 o[4];
#pragma unroll
        for (int k = 0; k < 4; k++) {
            float q = rintf(y[i * 4 + k] * scale);
            q = fminf(fmaxf(q, -128.0f), 127.0f);
            o[k] = __float2bfloat16(q);
        }
        *(uint2*)(g_A + (size_t)row * HDIM + (threadIdx.x + i * 256) * 4) = *(const uint2*)o;
    }
    if (threadIdx.x == 0) g_rs[row] = 1.0f / scale;
}

// ---------------- launch (R11 order; wreduce folded into tern) ----------------
extern "C" void kernel_launch(void* const* d_in, const int* in_sizes, int n_in,
                              void* d_out, int out_size) {
    const float* x  = (const float*)d_in[0];
    const float* W0 = (const float*)d_in[1];
    const float* W1 = (const float*)d_in[2];
    const float* W2 = (const float*)d_in[3];
    const float* W3 = (const float*)d_in[4];
    const float* g0 = (const float*)d_in[5];
    const float* b0 = (const float*)d_in[6];
    const float* g1 = (const float*)d_in[7];
    const float* b1 = (const float*)d_in[8];
    const float* g2 = (const float*)d_in[9];
    const float* b2 = (const float*)d_in[10];
    float* out = (float*)d_out;

    cudaFuncSetAttribute(gemm_bf16, cudaFuncAttributeMaxDynamicSharedMemorySize, GEMM_SMEM);

    const double c0 = (double)HDIM * DIN;
    const double c1 = (double)HDIM * HDIM;
    const double c3 = (double)NOUT * HDIM;

    wsum_kernel<<<1024, 256>>>(W0, HDIM * DIN, 0);
    wsum_kernel<<<1024, 256>>>(W1, HDIM * HDIM, 1);
    wsum_kernel<<<1024, 256>>>(W2, HDIM * HDIM, 2);
    wsum_kernel<<<1024, 256>>>(W3, NOUT * HDIM, 3);

    actquant_x<<<BATCH, 256>>>(x);

    // Layer 0: K=1024
    tern_kernel<<<1024, 256>>>(W0, HDIM, DIN, HDIM, 0, c0);
    gemm_bf16<<<dim3(HDIM / 128, BATCH / 128), 256, GEMM_SMEM>>>(DIN, HDIM, nullptr, c0);
    ln_silu_quant<<<BATCH, 256>>>(g0, b0, 0, c0);

    // Layer 1
    tern_kernel<<<1024, 256>>>(W1, HDIM, HDIM, HDIM, 1, c1);
    gemm_bf16<<<dim3(HDIM / 128, BATCH / 128), 256, GEMM_SMEM>>>(HDIM, HDIM, nullptr, c1);
    ln_silu_quant<<<BATCH, 256>>>(g1, b1, 1, c1);

    // Layer 2
    tern_kernel<<<1024, 256>>>(W2, HDIM, HDIM, HDIM, 2, c1);
    gemm_bf16<<<dim3(HDIM / 128, BATCH / 128), 256, GEMM_SMEM>>>(HDIM, HDIM, nullptr, c1);
    ln_silu_quant<<<BATCH, 256>>>(g2, b2, 2, c1);

    // Layer 3: output head, N padded 2000 -> 2048; fused sigmoid epilogue
    tern_kernel<<<1024, 256>>>(W3, NOUT, HDIM, NOUT_PAD, 3, c3);
    gemm_bf16<<<dim3(NOUT_PAD / 128, BATCH / 128), 256, GEMM_SMEM>>>(HDIM, NOUT_PAD, out, c3);
}

// round 16
// speedup vs baseline: 1.0129x; 1.0129x over previous
#include <cuda_runtime.h>
#include <cuda_bf16.h>
#include <cstdint>
#include <math.h>

#define EPSV 1e-5f
#define BATCH 4096
#define HDIM 4096
#define DIN 1024
#define NOUT 2000
#define NOUT_PAD 2048

// ---------------- scratch (device globals: allocation-free, <=134MB total) ----------------
__device__ __align__(16) __nv_bfloat16 g_A[BATCH * HDIM];   // quantized activations (int-valued bf16)
__device__ __align__(16) __nv_bfloat16 g_W[HDIM * HDIM];    // ternary weights (bf16), reused per layer
__device__ float  g_C[BATCH * HDIM];                        // raw GEMM output (integer-valued fp32)
__device__ float  g_rs[BATCH];                              // per-row activation dequant (1/scale)
__device__ float  g_wpart[4][1024];                         // per-block partial |W| sums
__device__ double g_wsum[4];                                // total |W| sums

// ================= helpers =================
__device__ __forceinline__ uint32_t smem_u32(const void* p) {
    uint32_t a;
    asm("{ .reg .u64 t; cvta.to.shared.u64 t, %1; cvt.u32.u64 %0, t; }" : "=r"(a) : "l"(p));
    return a;
}
__device__ __forceinline__ void cp16(uint32_t dst, const void* src) {
    asm volatile("cp.async.cg.shared.global [%0], [%1], 16;\n" :: "r"(dst), "l"(src));
}
#define CP_COMMIT() asm volatile("cp.async.commit_group;\n" ::: "memory")
#define CP_WAIT1()  asm volatile("cp.async.wait_group 1;\n" ::: "memory")

__device__ __forceinline__ void ldsm_x4(uint32_t& r0, uint32_t& r1, uint32_t& r2, uint32_t& r3,
                                        uint32_t addr) {
    asm volatile("ldmatrix.sync.aligned.m8n8.x4.shared.b16 {%0,%1,%2,%3}, [%4];"
                 : "=r"(r0), "=r"(r1), "=r"(r2), "=r"(r3) : "r"(addr));
}

// ---------------- reductions ----------------
__device__ __forceinline__ float blockReduceMax(float val) {
    __shared__ float sm[32];
    int lane = threadIdx.x & 31, wid = threadIdx.x >> 5;
#pragma unroll
    for (int o = 16; o; o >>= 1) val = fmaxf(val, __shfl_xor_sync(0xffffffffu, val, o));
    if (lane == 0) sm[wid] = val;
    __syncthreads();
    if (wid == 0) {
        val = (lane < (blockDim.x >> 5)) ? sm[lane] : 0.f;
#pragma unroll
        for (int o = 16; o; o >>= 1) val = fmaxf(val, __shfl_xor_sync(0xffffffffu, val, o));
        if (lane == 0) sm[0] = val;
    }
    __syncthreads();
    float r = sm[0];
    __syncthreads();
    return r;
}

// fused dual-sum block reduction: returns (sum of a, sum of b) to all threads
__device__ __forceinline__ float2 blockReduceSum2(float a, float b) {
    __shared__ float sma[32];
    __shared__ float smb[32];
    int lane = threadIdx.x & 31, wid = threadIdx.x >> 5;
#pragma unroll
    for (int o = 16; o; o >>= 1) {
        a += __shfl_xor_sync(0xffffffffu, a, o);
        b += __shfl_xor_sync(0xffffffffu, b, o);
    }
    if (lane == 0) { sma[wid] = a; smb[wid] = b; }
    __syncthreads();
    if (wid == 0) {
        a = (lane < (blockDim.x >> 5)) ? sma[lane] : 0.f;
        b = (lane < (blockDim.x >> 5)) ? smb[lane] : 0.f;
#pragma unroll
        for (int o = 16; o; o >>= 1) {
            a += __shfl_xor_sync(0xffffffffu, a, o);
            b += __shfl_xor_sync(0xffffffffu, b, o);
        }
        if (lane == 0) { sma[0] = a; smb[0] = b; }
    }
    __syncthreads();
    float2 r = make_float2(sma[0], smb[0]);
    __syncthreads();
    return r;
}

// ---------------- weight abs-mean pass 1 (fp32, deterministic, MLP-4) ----------------
__global__ void wsum_kernel(const float* __restrict__ W, int n, int idx) {
    const float4* W4 = (const float4*)W;
    const int n4 = n >> 2;
    const int str = gridDim.x * blockDim.x;
    float s = 0.0f;
    int i = blockIdx.x * blockDim.x + threadIdx.x;
    for (; i + 3 * str < n4; i += 4 * str) {
        float4 a = W4[i];
        float4 b = W4[i + str];
        float4 c = W4[i + 2 * str];
        float4 d = W4[i + 3 * str];
        s += fabsf(a.x) + fabsf(a.y) + fabsf(a.z) + fabsf(a.w);
        s += fabsf(b.x) + fabsf(b.y) + fabsf(b.z) + fabsf(b.w);
        s += fabsf(c.x) + fabsf(c.y) + fabsf(c.z) + fabsf(c.w);
        s += fabsf(d.x) + fabsf(d.y) + fabsf(d.z) + fabsf(d.w);
    }
    for (; i < n4; i += str) {
        float4 a = W4[i];
        s += fabsf(a.x) + fabsf(a.y) + fabsf(a.z) + fabsf(a.w);
    }
    __shared__ float sm[256];
    sm[threadIdx.x] = s;
    __syncthreads();
    for (int o = 128; o; o >>= 1) {
        if (threadIdx.x < o) sm[threadIdx.x] += sm[threadIdx.x + o];
        __syncthreads();
    }
    if (threadIdx.x == 0) g_wpart[idx][blockIdx.x] = sm[0];
}

__global__ void wreduce_kernel() {
    int idx = blockIdx.x;
    double s = 0.0;
    for (int i = threadIdx.x; i < 1024; i += 256) s += (double)g_wpart[idx][i];
    __shared__ double sm[256];
    sm[threadIdx.x] = s;
    __syncthreads();
    for (int o = 128; o; o >>= 1) {
        if (threadIdx.x < o) sm[threadIdx.x] += sm[threadIdx.x + o];
        __syncthreads();
    }
    if (threadIdx.x == 0) g_wsum[idx] = sm[0];
}

// ---------------- ternarize weights into bf16 scratch (16 elems/thread) ----------------
__global__ void tern_kernel(const float* __restrict__ W, int rows, int cols,
                            int rows_pad, int idx, double count) {
    float mean = (float)(g_wsum[idx] / count);
    float scale = 1.0f / fmaxf(mean, EPSV);
    int n16 = (rows_pad * cols) >> 4;   // cols % 16 == 0, chunks never straddle rows
    int str = gridDim.x * blockDim.x;
    for (int i16 = blockIdx.x * blockDim.x + threadIdx.x; i16 < n16; i16 += str) {
        int r = (i16 << 4) / cols;
        __nv_bfloat16 o[16];
        if (r < rows) {
            const float4* p = (const float4*)(W + ((size_t)i16 << 4));
            float4 a = p[0], b = p[1], c = p[2], d = p[3];
            float v[16] = {a.x, a.y, a.z, a.w, b.x, b.y, b.z, b.w,
                           c.x, c.y, c.z, c.w, d.x, d.y, d.z, d.w};
#pragma unroll
            for (int k = 0; k < 16; k++) {
                float t = rintf(v[k] * scale);
                o[k] = __float2bfloat16(fminf(fmaxf(t, -1.0f), 1.0f));
            }
        } else {
#pragma unroll
            for (int k = 0; k < 16; k++) o[k] = __float2bfloat16(0.0f);
        }
        *(uint4*)(g_W + ((size_t)i16 << 4)) = *(const uint4*)o;
        *(uint4*)(g_W + ((size_t)i16 << 4) + 8) = *(const uint4*)(o + 8);
    }
}

// ---------------- quantize input x (float4 path) ----------------
__global__ void actquant_x(const float* __restrict__ x) {
    int row = blockIdx.x;
    const float4* xr4 = (const float4*)(x + (size_t)row * DIN);
    float4 t = xr4[threadIdx.x];   // 256 threads x 4 = 1024
    float m = fmaxf(fmaxf(fabsf(t.x), fabsf(t.y)), fmaxf(fabsf(t.z), fabsf(t.w)));
    m = blockReduceMax(m);
    float scale = 127.0f / fmaxf(m, EPSV);
    float v[4] = {t.x, t.y, t.z, t.w};
    __nv_bfloat16 o[4];
#pragma unroll
    for (int k = 0; k < 4; k++) {
        float q = rintf(v[k] * scale);
        q = fminf(fmaxf(q, -128.0f), 127.0f);
        o[k] = __float2bfloat16(q);
    }
    *(uint2*)(g_A + (size_t)row * DIN + threadIdx.x * 4) = *(const uint2*)o;
    if (threadIdx.x == 0) g_rs[row] = 1.0f / scale;
}

// ================ bf16 HMMA GEMM: C[M,N] = g_A[M,K] @ g_W[N,K]^T ================
// 128x128 CTA tile, 8 warps (2x4), warp tile 64x32, K chunk 64,
// 3-stage cp.async ring with ONE barrier per chunk, ldmatrix fragment loads.
// If outp != nullptr (layer 3): fused sigmoid epilogue writes final outputs.
#define SROWE 72
#define STAGE_B (128 * SROWE * 2)          // 18432
#define GEMM_SMEM (6 * STAGE_B)            // 110592

__global__ __launch_bounds__(256, 2) void gemm_bf16(int K, int ldc,
                                                    float* __restrict__ outp, double count) {
    extern __shared__ __align__(16) char smem[];
    const uint32_t sbase = smem_u32(smem);
    const int tid = threadIdx.x;
    const int lane = tid & 31;
    const int wid = tid >> 5;
    const int wm = (wid >> 2) * 64;   // warp M offset (0/64)
    const int wn = (wid & 3) * 32;    // warp N offset (0..96)
    const int bm = blockIdx.y * 128;
    const int bn = blockIdx.x * 128;
    const int NC = K >> 6;            // 64-wide K chunks

    const __nv_bfloat16* Ag = g_A + (size_t)bm * K;
    const __nv_bfloat16* Bg = g_W + (size_t)bn * K;

    const int lrow = tid >> 1;            // 0..127 row
    const int lj = (tid & 1) * 4;         // 16B chunks {0..3} or {4..7}

    auto load_chunk = [&](int c, int buf) {
        int k0 = c << 6;
        uint32_t da = sbase + buf * 2 * STAGE_B;
        uint32_t db = da + STAGE_B;
        const __nv_bfloat16* arow = Ag + (size_t)lrow * K + k0;
        const __nv_bfloat16* brow = Bg + (size_t)lrow * K + k0;
        uint32_t off = lrow * (SROWE * 2) + lj * 16;
#pragma unroll
        for (int j = 0; j < 4; j++) {
            cp16(da + off + j * 16, arow + (lj + j) * 8);
            cp16(db + off + j * 16, brow + (lj + j) * 8);
        }
    };

    float acc[4][4][4];
#pragma unroll
    for (int i = 0; i < 4; i++)
#pragma unroll
        for (int j = 0; j < 4; j++)
#pragma unroll
            for (int k = 0; k < 4; k++) acc[i][j][k] = 0.0f;

    // prologue: chunks 0 and 1 in flight
    load_chunk(0, 0);
    CP_COMMIT();
    if (NC > 1) load_chunk(1, 1);
    CP_COMMIT();

    // ldmatrix lane addressing
    const int a_row_off = (lane & 7) + ((lane >> 3) & 1) * 8;
    const int a_col_off = (lane >> 4) * 8;
    const int b_row_off = (lane & 7) + ((lane >> 4) & 1) * 8;
    const int b_col_off = ((lane >> 3) & 1) * 8;

    int buf = 0;          // = c % 3
    int buf2 = 2;         // = (c+2) % 3
    for (int c = 0; c < NC; c++) {
        CP_WAIT1();       // chunk c resident (<=1 newer group outstanding)
        __syncthreads();  // prior reads of buf2 done across CTA

        if (c + 2 < NC) load_chunk(c + 2, buf2);
        CP_COMMIT();      // keep group count in lockstep

        uint32_t Abase = sbase + buf * 2 * STAGE_B;
        uint32_t Bbase = Abase + STAGE_B;

#pragma unroll
        for (int kk = 0; kk < 64; kk += 16) {
            uint32_t af[4][4];
#pragma unroll
            for (int mi = 0; mi < 4; mi++) {
                uint32_t addr = Abase + (uint32_t)((wm + mi * 16 + a_row_off) * (SROWE * 2)
                                                   + (kk + a_col_off) * 2);
                ldsm_x4(af[mi][0], af[mi][1], af[mi][2], af[mi][3], addr);
            }
            uint32_t bfr[4][2];
#pragma unroll
            for (int nip = 0; nip < 2; nip++) {
                uint32_t addr = Bbase + (uint32_t)((wn + nip * 16 + b_row_off) * (SROWE * 2)
                                                   + (kk + b_col_off) * 2);
                ldsm_x4(bfr[nip * 2][0], bfr[nip * 2][1],
                        bfr[nip * 2 + 1][0], bfr[nip * 2 + 1][1], addr);
            }
#pragma unroll
            for (int mi = 0; mi < 4; mi++)
#pragma unroll
                for (int ni = 0; ni < 4; ni++)
                    asm volatile(
                        "mma.sync.aligned.m16n8k16.row.col.f32.bf16.bf16.f32 "
                        "{%0,%1,%2,%3}, {%4,%5,%6,%7}, {%8,%9}, {%0,%1,%2,%3};\n"
                        : "+f"(acc[mi][ni][0]), "+f"(acc[mi][ni][1]),
                          "+f"(acc[mi][ni][2]), "+f"(acc[mi][ni][3])
                        : "r"(af[mi][0]), "r"(af[mi][1]), "r"(af[mi][2]), "r"(af[mi][3]),
                          "r"(bfr[ni][0]), "r"(bfr[ni][1]));
        }
        buf = (buf == 2) ? 0 : buf + 1;
        buf2 = (buf2 == 2) ? 0 : buf2 + 1;
    }

    if (outp == nullptr) {
#pragma unroll
        for (int mi = 0; mi < 4; mi++) {
#pragma unroll
            for (int ni = 0; ni < 4; ni++) {
                int r = bm + wm + mi * 16 + (lane >> 2);
                int cc = bn + wn + ni * 8 + (lane & 3) * 2;
                *(float2*)&g_C[(size_t)r * ldc + cc] = make_float2(acc[mi][ni][0], acc[mi][ni][1]);
                *(float2*)&g_C[(size_t)(r + 8) * ldc + cc] = make_float2(acc[mi][ni][2], acc[mi][ni][3]);
            }
        }
    } else {
        // fused final epilogue: logits -> sigmoid outputs, skip padded cols
        float wmean = fmaxf((float)(g_wsum[3] / count), EPSV);
#pragma unroll
        for (int mi = 0; mi < 4; mi++) {
            int r0 = bm + wm + mi * 16 + (lane >> 2);
            float f0 = __ldg(&g_rs[r0]) * wmean;
            float f1 = __ldg(&g_rs[r0 + 8]) * wmean;
#pragma unroll
            for (int ni = 0; ni < 4; ni++) {
                int cc = bn + wn + ni * 8 + (lane & 3) * 2;
                if (cc < 2000) {
                    float va0 = acc[mi][ni][0] * f0, va1 = acc[mi][ni][1] * f0;
                    float vb0 = acc[mi][ni][2] * f1, vb1 = acc[mi][ni][3] * f1;
                    size_t base0, base1;
                    float kmul, kadd;
                    if (cc < 1000) {            // mz half
                        base0 = (size_t)r0 * 1000 + cc;
                        base1 = (size_t)(r0 + 8) * 1000 + cc;
                        kmul = 999.0f; kadd = 1.0f;
                    } else {                    // intensity half
                        base0 = (size_t)BATCH * 1000 + (size_t)r0 * 1000 + (cc - 1000);
                        base1 = (size_t)BATCH * 1000 + (size_t)(r0 + 8) * 1000 + (cc - 1000);
                        kmul = 100.0f; kadd = 0.0f;
                    }
                    *(float2*)&outp[base0] = make_float2(
                        kmul / (1.0f + __expf(-va0)) + kadd,
                        kmul / (1.0f + __expf(-va1)) + kadd);
                    *(float2*)&outp[base1] = make_float2(
                        kmul / (1.0f + __expf(-vb0)) + kadd,
                        kmul / (1.0f + __expf(-vb1)) + kadd);
                }
            }
        }
    }
}

// ---------------- fused scale + LayerNorm + SiLU + re-quantize (single-pass moments) ----------------
__global__ void ln_silu_quant(const float* __restrict__ gamma, const float* __restrict__ beta,
                              int widx, double count) {
    int row = blockIdx.x;
    float wmean = fmaxf((float)(g_wsum[widx] / count), EPSV);
    float f = g_rs[row] * wmean;
    const float4* cr4 = (const float4*)(g_C + (size_t)row * HDIM);
    const float4* g4 = (const float4*)gamma;
    const float4* b4 = (const float4*)beta;

    float v[16];
    float s = 0.0f, sq = 0.0f;
#pragma unroll
    for (int i = 0; i < 4; i++) {
        float4 t = cr4[threadIdx.x + i * 256];
        v[i * 4 + 0] = t.x * f; v[i * 4 + 1] = t.y * f;
        v[i * 4 + 2] = t.z * f; v[i * 4 + 3] = t.w * f;
#pragma unroll
        for (int k = 0; k < 4; k++) {
            float x = v[i * 4 + k];
            s += x;
            sq = fmaf(x, x, sq);
        }
    }
    float2 ss = blockReduceSum2(s, sq);
    float mu = ss.x * (1.0f / HDIM);
    float var = fmaxf(ss.y * (1.0f / HDIM) - mu * mu, 0.0f);
    float inv_std = rsqrtf(var + EPSV);

    float y[16];
    float mx = 0.0f;
#pragma unroll
    for (int i = 0; i < 4; i++) {
        float4 gg = g4[threadIdx.x + i * 256];
        float4 bb = b4[threadIdx.x + i * 256];
        float gv[4] = {gg.x, gg.y, gg.z, gg.w};
        float bv[4] = {bb.x, bb.y, bb.z, bb.w};
#pragma unroll
        for (int k = 0; k < 4; k++) {
            float t = (v[i * 4 + k] - mu) * inv_std * gv[k] + bv[k];
            t = t / (1.0f + __expf(-t));  // silu
            y[i * 4 + k] = t;
            mx = fmaxf(mx, fabsf(t));
        }
    }
    mx = blockReduceMax(mx);
    float scale = 127.0f / fmaxf(mx, EPSV);
#pragma unroll
    for (int i = 0; i < 4; i++) {
        __nv_bfloat16 o[4];
#pragma unroll
        for (int k = 0; k < 4; k++) {
            float q = rintf(y[i * 4 + k] * scale);
            q = fminf(fmaxf(q, -128.0f), 127.0f);
            o[k] = __float2bfloat16(q);
        }
        *(uint2*)(g_A + (size_t)row * HDIM + (threadIdx.x + i * 256) * 4) = *(const uint2*)o;
    }
    if (threadIdx.x == 0) g_rs[row] = 1.0f / scale;
}

// ---------------- launch (R11 structure) ----------------
extern "C" void kernel_launch(void* const* d_in, const int* in_sizes, int n_in,
                              void* d_out, int out_size) {
    const float* x  = (const float*)d_in[0];
    const float* W0 = (const float*)d_in[1];
    const float* W1 = (const float*)d_in[2];
    const float* W2 = (const float*)d_in[3];
    const float* W3 = (const float*)d_in[4];
    const float* g0 = (const float*)d_in[5];
    const float* b0 = (const float*)d_in[6];
    const float* g1 = (const float*)d_in[7];
    const float* b1 = (const float*)d_in[8];
    const float* g2 = (const float*)d_in[9];
    const float* b2 = (const float*)d_in[10];
    float* out = (float*)d_out;

    cudaFuncSetAttribute(gemm_bf16, cudaFuncAttributeMaxDynamicSharedMemorySize, GEMM_SMEM);

    const double c0 = (double)HDIM * DIN;
    const double c1 = (double)HDIM * HDIM;
    const double c3 = (double)NOUT * HDIM;

    wsum_kernel<<<1024, 256>>>(W0, HDIM * DIN, 0);
    wsum_kernel<<<1024, 256>>>(W1, HDIM * HDIM, 1);
    wsum_kernel<<<1024, 256>>>(W2, HDIM * HDIM, 2);
    wsum_kernel<<<1024, 256>>>(W3, NOUT * HDIM, 3);
    wreduce_kernel<<<4, 256>>>();

    actquant_x<<<BATCH, 256>>>(x);

    // Layer 0: K=1024
    tern_kernel<<<1024, 256>>>(W0, HDIM, DIN, HDIM, 0, c0);
    gemm_bf16<<<dim3(HDIM / 128, BATCH / 128), 256, GEMM_SMEM>>>(DIN, HDIM, nullptr, c0);
    ln_silu_quant<<<BATCH, 256>>>(g0, b0, 0, c0);

    // Layer 1
    tern_kernel<<<1024, 256>>>(W1, HDIM, HDIM, HDIM, 1, c1);
    gemm_bf16<<<dim3(HDIM / 128, BATCH / 128), 256, GEMM_SMEM>>>(HDIM, HDIM, nullptr, c1);
    ln_silu_quant<<<BATCH, 256>>>(g1, b1, 1, c1);

    // Layer 2
    tern_kernel<<<1024, 256>>>(W2, HDIM, HDIM, HDIM, 2, c1);
    gemm_bf16<<<dim3(HDIM / 128, BATCH / 128), 256, GEMM_SMEM>>>(HDIM, HDIM, nullptr, c1);
    ln_silu_quant<<<BATCH, 256>>>(g2, b2, 2, c1);

    // Layer 3: output head, N padded 2000 -> 2048; fused sigmoid epilogue
    tern_kernel<<<1024, 256>>>(W3, NOUT, HDIM, NOUT_PAD, 3, c3);
    gemm_bf16<<<dim3(NOUT_PAD / 128, BATCH / 128), 256, GEMM_SMEM>>>(HDIM, NOUT_PAD, out, c3);
}

// round 17
// speedup vs baseline: 1.0148x; 1.0020x over previous
#include <cuda_runtime.h>
#include <cuda_bf16.h>
#include <cstdint>
#include <math.h>

#define EPSV 1e-5f
#define BATCH 4096
#define HDIM 4096
#define DIN 1024
#define NOUT 2000
#define NOUT_PAD 2048

// ---------------- scratch (device globals: allocation-free, <=134MB total) ----------------
__device__ __align__(16) __nv_bfloat16 g_A[BATCH * HDIM];   // quantized activations (int-valued bf16)
__device__ __align__(16) __nv_bfloat16 g_W[HDIM * HDIM];    // ternary weights (bf16), reused per layer
__device__ float  g_C[BATCH * HDIM];                        // raw GEMM output (integer-valued fp32)
__device__ float  g_rs[BATCH];                              // per-row activation dequant (1/scale)
__device__ float  g_wpart[4][1024];                         // per-block partial |W| sums
__device__ double g_wsum[4];                                // total |W| sums

// ================= helpers =================
__device__ __forceinline__ uint32_t smem_u32(const void* p) {
    uint32_t a;
    asm("{ .reg .u64 t; cvta.to.shared.u64 t, %1; cvt.u32.u64 %0, t; }" : "=r"(a) : "l"(p));
    return a;
}
__device__ __forceinline__ void cp16(uint32_t dst, const void* src) {
    asm volatile("cp.async.cg.shared.global [%0], [%1], 16;\n" :: "r"(dst), "l"(src));
}
#define CP_COMMIT() asm volatile("cp.async.commit_group;\n" ::: "memory")
#define CP_WAIT1()  asm volatile("cp.async.wait_group 1;\n" ::: "memory")

__device__ __forceinline__ void ldsm_x4(uint32_t& r0, uint32_t& r1, uint32_t& r2, uint32_t& r3,
                                        uint32_t addr) {
    asm volatile("ldmatrix.sync.aligned.m8n8.x4.shared.b16 {%0,%1,%2,%3}, [%4];"
                 : "=r"(r0), "=r"(r1), "=r"(r2), "=r"(r3) : "r"(addr));
}

// ---------------- reductions ----------------
__device__ __forceinline__ float blockReduceMax(float val) {
    __shared__ float sm[32];
    int lane = threadIdx.x & 31, wid = threadIdx.x >> 5;
#pragma unroll
    for (int o = 16; o; o >>= 1) val = fmaxf(val, __shfl_xor_sync(0xffffffffu, val, o));
    if (lane == 0) sm[wid] = val;
    __syncthreads();
    if (wid == 0) {
        val = (lane < (blockDim.x >> 5)) ? sm[lane] : 0.f;
#pragma unroll
        for (int o = 16; o; o >>= 1) val = fmaxf(val, __shfl_xor_sync(0xffffffffu, val, o));
        if (lane == 0) sm[0] = val;
    }
    __syncthreads();
    float r = sm[0];
    __syncthreads();
    return r;
}

// fused dual-sum block reduction: returns (sum of a, sum of b) to all threads
__device__ __forceinline__ float2 blockReduceSum2(float a, float b) {
    __shared__ float sma[32];
    __shared__ float smb[32];
    int lane = threadIdx.x & 31, wid = threadIdx.x >> 5;
#pragma unroll
    for (int o = 16; o; o >>= 1) {
        a += __shfl_xor_sync(0xffffffffu, a, o);
        b += __shfl_xor_sync(0xffffffffu, b, o);
    }
    if (lane == 0) { sma[wid] = a; smb[wid] = b; }
    __syncthreads();
    if (wid == 0) {
        a = (lane < (blockDim.x >> 5)) ? sma[lane] : 0.f;
        b = (lane < (blockDim.x >> 5)) ? smb[lane] : 0.f;
#pragma unroll
        for (int o = 16; o; o >>= 1) {
            a += __shfl_xor_sync(0xffffffffu, a, o);
            b += __shfl_xor_sync(0xffffffffu, b, o);
        }
        if (lane == 0) { sma[0] = a; smb[0] = b; }
    }
    __syncthreads();
    float2 r = make_float2(sma[0], smb[0]);
    __syncthreads();
    return r;
}

// ---------------- batched weight abs-mean pass 1 (all 4 matrices, one launch) ----------------
// gridDim = (1024, 4); blockIdx.y selects matrix. Per-matrix partial layout and
// per-thread summation order identical to the previous per-matrix wsum_kernel.
__global__ void wsum4_kernel(const float* __restrict__ Wa, int na,
                             const float* __restrict__ Wb, int nb,
                             const float* __restrict__ Wc, int nc,
                             const float* __restrict__ Wd, int nd) {
    int idx = blockIdx.y;
    const float* W = (idx == 0) ? Wa : (idx == 1) ? Wb : (idx == 2) ? Wc : Wd;
    int n = (idx == 0) ? na : (idx == 1) ? nb : (idx == 2) ? nc : nd;

    const float4* W4 = (const float4*)W;
    const int n4 = n >> 2;
    const int str = gridDim.x * blockDim.x;
    float s = 0.0f;
    int i = blockIdx.x * blockDim.x + threadIdx.x;
    for (; i + 3 * str < n4; i += 4 * str) {
        float4 a = W4[i];
        float4 b = W4[i + str];
        float4 c = W4[i + 2 * str];
        float4 d = W4[i + 3 * str];
        s += fabsf(a.x) + fabsf(a.y) + fabsf(a.z) + fabsf(a.w);
        s += fabsf(b.x) + fabsf(b.y) + fabsf(b.z) + fabsf(b.w);
        s += fabsf(c.x) + fabsf(c.y) + fabsf(c.z) + fabsf(c.w);
        s += fabsf(d.x) + fabsf(d.y) + fabsf(d.z) + fabsf(d.w);
    }
    for (; i < n4; i += str) {
        float4 a = W4[i];
        s += fabsf(a.x) + fabsf(a.y) + fabsf(a.z) + fabsf(a.w);
    }
    __shared__ float sm[256];
    sm[threadIdx.x] = s;
    __syncthreads();
    for (int o = 128; o; o >>= 1) {
        if (threadIdx.x < o) sm[threadIdx.x] += sm[threadIdx.x + o];
        __syncthreads();
    }
    if (threadIdx.x == 0) g_wpart[idx][blockIdx.x] = sm[0];
}

__global__ void wreduce_kernel() {
    int idx = blockIdx.x;
    double s = 0.0;
    for (int i = threadIdx.x; i < 1024; i += 256) s += (double)g_wpart[idx][i];
    __shared__ double sm[256];
    sm[threadIdx.x] = s;
    __syncthreads();
    for (int o = 128; o; o >>= 1) {
        if (threadIdx.x < o) sm[threadIdx.x] += sm[threadIdx.x + o];
        __syncthreads();
    }
    if (threadIdx.x == 0) g_wsum[idx] = sm[0];
}

// ---------------- ternarize weights into bf16 scratch (16 elems/thread) ----------------
__global__ void tern_kernel(const float* __restrict__ W, int rows, int cols,
                            int rows_pad, int idx, double count) {
    float mean = (float)(g_wsum[idx] / count);
    float scale = 1.0f / fmaxf(mean, EPSV);
    int n16 = (rows_pad * cols) >> 4;   // cols % 16 == 0, chunks never straddle rows
    int str = gridDim.x * blockDim.x;
    for (int i16 = blockIdx.x * blockDim.x + threadIdx.x; i16 < n16; i16 += str) {
        int r = (i16 << 4) / cols;
        __nv_bfloat16 o[16];
        if (r < rows) {
            const float4* p = (const float4*)(W + ((size_t)i16 << 4));
            float4 a = p[0], b = p[1], c = p[2], d = p[3];
            float v[16] = {a.x, a.y, a.z, a.w, b.x, b.y, b.z, b.w,
                           c.x, c.y, c.z, c.w, d.x, d.y, d.z, d.w};
#pragma unroll
            for (int k = 0; k < 16; k++) {
                float t = rintf(v[k] * scale);
                o[k] = __float2bfloat16(fminf(fmaxf(t, -1.0f), 1.0f));
            }
        } else {
#pragma unroll
            for (int k = 0; k < 16; k++) o[k] = __float2bfloat16(0.0f);
        }
        *(uint4*)(g_W + ((size_t)i16 << 4)) = *(const uint4*)o;
        *(uint4*)(g_W + ((size_t)i16 << 4) + 8) = *(const uint4*)(o + 8);
    }
}

// ---------------- quantize input x (float4 path) ----------------
__global__ void actquant_x(const float* __restrict__ x) {
    int row = blockIdx.x;
    const float4* xr4 = (const float4*)(x + (size_t)row * DIN);
    float4 t = xr4[threadIdx.x];   // 256 threads x 4 = 1024
    float m = fmaxf(fmaxf(fabsf(t.x), fabsf(t.y)), fmaxf(fabsf(t.z), fabsf(t.w)));
    m = blockReduceMax(m);
    float scale = 127.0f / fmaxf(m, EPSV);
    float v[4] = {t.x, t.y, t.z, t.w};
    __nv_bfloat16 o[4];
#pragma unroll
    for (int k = 0; k < 4; k++) {
        float q = rintf(v[k] * scale);
        q = fminf(fmaxf(q, -128.0f), 127.0f);
        o[k] = __float2bfloat16(q);
    }
    *(uint2*)(g_A + (size_t)row * DIN + threadIdx.x * 4) = *(const uint2*)o;
    if (threadIdx.x == 0) g_rs[row] = 1.0f / scale;
}

// ================ bf16 HMMA GEMM: C[M,N] = g_A[M,K] @ g_W[N,K]^T ================
// 128x128 CTA tile, 8 warps (2x4), warp tile 64x32, K chunk 64,
// 3-stage cp.async ring with ONE barrier per chunk, ldmatrix fragment loads.
// If outp != nullptr (layer 3): fused sigmoid epilogue writes final outputs.
#define SROWE 72
#define STAGE_B (128 * SROWE * 2)          // 18432
#define GEMM_SMEM (6 * STAGE_B)            // 110592

__global__ __launch_bounds__(256, 2) void gemm_bf16(int K, int ldc,
                                                    float* __restrict__ outp, double count) {
    extern __shared__ __align__(16) char smem[];
    const uint32_t sbase = smem_u32(smem);
    const int tid = threadIdx.x;
    const int lane = tid & 31;
    const int wid = tid >> 5;
    const int wm = (wid >> 2) * 64;   // warp M offset (0/64)
    const int wn = (wid & 3) * 32;    // warp N offset (0..96)
    const int bm = blockIdx.y * 128;
    const int bn = blockIdx.x * 128;
    const int NC = K >> 6;            // 64-wide K chunks

    const __nv_bfloat16* Ag = g_A + (size_t)bm * K;
    const __nv_bfloat16* Bg = g_W + (size_t)bn * K;

    const int lrow = tid >> 1;            // 0..127 row
    const int lj = (tid & 1) * 4;         // 16B chunks {0..3} or {4..7}

    auto load_chunk = [&](int c, int buf) {
        int k0 = c << 6;
        uint32_t da = sbase + buf * 2 * STAGE_B;
        uint32_t db = da + STAGE_B;
        const __nv_bfloat16* arow = Ag + (size_t)lrow * K + k0;
        const __nv_bfloat16* brow = Bg + (size_t)lrow * K + k0;
        uint32_t off = lrow * (SROWE * 2) + lj * 16;
#pragma unroll
        for (int j = 0; j < 4; j++) {
            cp16(da + off + j * 16, arow + (lj + j) * 8);
            cp16(db + off + j * 16, brow + (lj + j) * 8);
        }
    };

    float acc[4][4][4];
#pragma unroll
    for (int i = 0; i < 4; i++)
#pragma unroll
        for (int j = 0; j < 4; j++)
#pragma unroll
            for (int k = 0; k < 4; k++) acc[i][j][k] = 0.0f;

    // prologue: chunks 0 and 1 in flight
    load_chunk(0, 0);
    CP_COMMIT();
    if (NC > 1) load_chunk(1, 1);
    CP_COMMIT();

    // ldmatrix lane addressing
    const int a_row_off = (lane & 7) + ((lane >> 3) & 1) * 8;
    const int a_col_off = (lane >> 4) * 8;
    const int b_row_off = (lane & 7) + ((lane >> 4) & 1) * 8;
    const int b_col_off = ((lane >> 3) & 1) * 8;

    int buf = 0;          // = c % 3
    int buf2 = 2;         // = (c+2) % 3
    for (int c = 0; c < NC; c++) {
        CP_WAIT1();       // chunk c resident (<=1 newer group outstanding)
        __syncthreads();  // prior reads of buf2 done across CTA

        if (c + 2 < NC) load_chunk(c + 2, buf2);
        CP_COMMIT();      // keep group count in lockstep

        uint32_t Abase = sbase + buf * 2 * STAGE_B;
        uint32_t Bbase = Abase + STAGE_B;

#pragma unroll
        for (int kk = 0; kk < 64; kk += 16) {
            uint32_t af[4][4];
#pragma unroll
            for (int mi = 0; mi < 4; mi++) {
                uint32_t addr = Abase + (uint32_t)((wm + mi * 16 + a_row_off) * (SROWE * 2)
                                                   + (kk + a_col_off) * 2);
                ldsm_x4(af[mi][0], af[mi][1], af[mi][2], af[mi][3], addr);
            }
            uint32_t bfr[4][2];
#pragma unroll
            for (int nip = 0; nip < 2; nip++) {
                uint32_t addr = Bbase + (uint32_t)((wn + nip * 16 + b_row_off) * (SROWE * 2)
                                                   + (kk + b_col_off) * 2);
                ldsm_x4(bfr[nip * 2][0], bfr[nip * 2][1],
                        bfr[nip * 2 + 1][0], bfr[nip * 2 + 1][1], addr);
            }
#pragma unroll
            for (int mi = 0; mi < 4; mi++)
#pragma unroll
                for (int ni = 0; ni < 4; ni++)
                    asm volatile(
                        "mma.sync.aligned.m16n8k16.row.col.f32.bf16.bf16.f32 "
                        "{%0,%1,%2,%3}, {%4,%5,%6,%7}, {%8,%9}, {%0,%1,%2,%3};\n"
                        : "+f"(acc[mi][ni][0]), "+f"(acc[mi][ni][1]),
                          "+f"(acc[mi][ni][2]), "+f"(acc[mi][ni][3])
                        : "r"(af[mi][0]), "r"(af[mi][1]), "r"(af[mi][2]), "r"(af[mi][3]),
                          "r"(bfr[ni][0]), "r"(bfr[ni][1]));
        }
        buf = (buf == 2) ? 0 : buf + 1;
        buf2 = (buf2 == 2) ? 0 : buf2 + 1;
    }

    if (outp == nullptr) {
#pragma unroll
        for (int mi = 0; mi < 4; mi++) {
#pragma unroll
            for (int ni = 0; ni < 4; ni++) {
                int r = bm + wm + mi * 16 + (lane >> 2);
                int cc = bn + wn + ni * 8 + (lane & 3) * 2;
                *(float2*)&g_C[(size_t)r * ldc + cc] = make_float2(acc[mi][ni][0], acc[mi][ni][1]);
                *(float2*)&g_C[(size_t)(r + 8) * ldc + cc] = make_float2(acc[mi][ni][2], acc[mi][ni][3]);
            }
        }
    } else {
        // fused final epilogue: logits -> sigmoid outputs, skip padded cols
        float wmean = fmaxf((float)(g_wsum[3] / count), EPSV);
#pragma unroll
        for (int mi = 0; mi < 4; mi++) {
            int r0 = bm + wm + mi * 16 + (lane >> 2);
            float f0 = __ldg(&g_rs[r0]) * wmean;
            float f1 = __ldg(&g_rs[r0 + 8]) * wmean;
#pragma unroll
            for (int ni = 0; ni < 4; ni++) {
                int cc = bn + wn + ni * 8 + (lane & 3) * 2;
                if (cc < 2000) {
                    float va0 = acc[mi][ni][0] * f0, va1 = acc[mi][ni][1] * f0;
                    float vb0 = acc[mi][ni][2] * f1, vb1 = acc[mi][ni][3] * f1;
                    size_t base0, base1;
                    float kmul, kadd;
                    if (cc < 1000) {            // mz half
                        base0 = (size_t)r0 * 1000 + cc;
                        base1 = (size_t)(r0 + 8) * 1000 + cc;
                        kmul = 999.0f; kadd = 1.0f;
                    } else {                    // intensity half
                        base0 = (size_t)BATCH * 1000 + (size_t)r0 * 1000 + (cc - 1000);
                        base1 = (size_t)BATCH * 1000 + (size_t)(r0 + 8) * 1000 + (cc - 1000);
                        kmul = 100.0f; kadd = 0.0f;
                    }
                    *(float2*)&outp[base0] = make_float2(
                        kmul / (1.0f + __expf(-va0)) + kadd,
                        kmul / (1.0f + __expf(-va1)) + kadd);
                    *(float2*)&outp[base1] = make_float2(
                        kmul / (1.0f + __expf(-vb0)) + kadd,
                        kmul / (1.0f + __expf(-vb1)) + kadd);
                }
            }
        }
    }
}

// ---------------- fused scale + LayerNorm + SiLU + re-quantize (single-pass moments) ----------------
__global__ void ln_silu_quant(const float* __restrict__ gamma, const float* __restrict__ beta,
                              int widx, double count) {
    int row = blockIdx.x;
    float wmean = fmaxf((float)(g_wsum[widx] / count), EPSV);
    float f = g_rs[row] * wmean;
    const float4* cr4 = (const float4*)(g_C + (size_t)row * HDIM);
    const float4* g4 = (const float4*)gamma;
    const float4* b4 = (const float4*)beta;

    float v[16];
    float s = 0.0f, sq = 0.0f;
#pragma unroll
    for (int i = 0; i < 4; i++) {
        float4 t = cr4[threadIdx.x + i * 256];
        v[i * 4 + 0] = t.x * f; v[i * 4 + 1] = t.y * f;
        v[i * 4 + 2] = t.z * f; v[i * 4 + 3] = t.w * f;
#pragma unroll
        for (int k = 0; k < 4; k++) {
            float x = v[i * 4 + k];
            s += x;
            sq = fmaf(x, x, sq);
        }
    }
    float2 ss = blockReduceSum2(s, sq);
    float mu = ss.x * (1.0f / HDIM);
    float var = fmaxf(ss.y * (1.0f / HDIM) - mu * mu, 0.0f);
    float inv_std = rsqrtf(var + EPSV);

    float y[16];
    float mx = 0.0f;
#pragma unroll
    for (int i = 0; i < 4; i++) {
        float4 gg = g4[threadIdx.x + i * 256];
        float4 bb = b4[threadIdx.x + i * 256];
        float gv[4] = {gg.x, gg.y, gg.z, gg.w};
        float bv[4] = {bb.x, bb.y, bb.z, bb.w};
#pragma unroll
        for (int k = 0; k < 4; k++) {
            float t = (v[i * 4 + k] - mu) * inv_std * gv[k] + bv[k];
            t = t / (1.0f + __expf(-t));  // silu
            y[i * 4 + k] = t;
            mx = fmaxf(mx, fabsf(t));
        }
    }
    mx = blockReduceMax(mx);
    float scale = 127.0f / fmaxf(mx, EPSV);
#pragma unroll
    for (int i = 0; i < 4; i++) {
        __nv_bfloat16 o[4];
#pragma unroll
        for (int k = 0; k < 4; k++) {
            float q = rintf(y[i * 4 + k] * scale);
            q = fminf(fmaxf(q, -128.0f), 127.0f);
            o[k] = __float2bfloat16(q);
        }
        *(uint2*)(g_A + (size_t)row * HDIM + (threadIdx.x + i * 256) * 4) = *(const uint2*)o;
    }
    if (threadIdx.x == 0) g_rs[row] = 1.0f / scale;
}

// ---------------- launch ----------------
extern "C" void kernel_launch(void* const* d_in, const int* in_sizes, int n_in,
                              void* d_out, int out_size) {
    const float* x  = (const float*)d_in[0];
    const float* W0 = (const float*)d_in[1];
    const float* W1 = (const float*)d_in[2];
    const float* W2 = (const float*)d_in[3];
    const float* W3 = (const float*)d_in[4];
    const float* g0 = (const float*)d_in[5];
    const float* b0 = (const float*)d_in[6];
    const float* g1 = (const float*)d_in[7];
    const float* b1 = (const float*)d_in[8];
    const float* g2 = (const float*)d_in[9];
    const float* b2 = (const float*)d_in[10];
    float* out = (float*)d_out;

    cudaFuncSetAttribute(gemm_bf16, cudaFuncAttributeMaxDynamicSharedMemorySize, GEMM_SMEM);

    const double c0 = (double)HDIM * DIN;
    const double c1 = (double)HDIM * HDIM;
    const double c3 = (double)NOUT * HDIM;

    // all four weight abs-sums in one launch
    wsum4_kernel<<<dim3(1024, 4), 256>>>(W0, HDIM * DIN, W1, HDIM * HDIM,
                                         W2, HDIM * HDIM, W3, NOUT * HDIM);
    wreduce_kernel<<<4, 256>>>();

    actquant_x<<<BATCH, 256>>>(x);

    // Layer 0: K=1024
    tern_kernel<<<1024, 256>>>(W0, HDIM, DIN, HDIM, 0, c0);
    gemm_bf16<<<dim3(HDIM / 128, BATCH / 128), 256, GEMM_SMEM>>>(DIN, HDIM, nullptr, c0);
    ln_silu_quant<<<BATCH, 256>>>(g0, b0, 0, c0);

    // Layer 1
    tern_kernel<<<1024, 256>>>(W1, HDIM, HDIM, HDIM, 1, c1);
    gemm_bf16<<<dim3(HDIM / 128, BATCH / 128), 256, GEMM_SMEM>>>(HDIM, HDIM, nullptr, c1);
    ln_silu_quant<<<BATCH, 256>>>(g1, b1, 1, c1);

    // Layer 2
    tern_kernel<<<1024, 256>>>(W2, HDIM, HDIM, HDIM, 2, c1);
    gemm_bf16<<<dim3(HDIM / 128, BATCH / 128), 256, GEMM_SMEM>>>(HDIM, HDIM, nullptr, c1);
    ln_silu_quant<<<BATCH, 256>>>(g2, b2, 2, c1);

    // Layer 3: output head, N padded 2000 -> 2048; fused sigmoid epilogue
    tern_kernel<<<1024, 256>>>(W3, NOUT, HDIM, NOUT_PAD, 3, c3);
    gemm_bf16<<<dim3(NOUT_PAD / 128, BATCH / 128), 256, GEMM_SMEM>>>(HDIM, NOUT_PAD, out, c3);
}